// round 3
// baseline (speedup 1.0000x reference)
#include <cuda_runtime.h>

// Problem constants (reference: N_NODES=100000, N_EDGES=1600000, D=64)
#define NODES_MAX 100000
#define D 64

// Scratch (sanctioned __device__ globals; no runtime allocation)
__device__ float g_base[NODES_MAX * D];   // feat@W1^T + b1 + b2, then += scattered temb
__device__ float g_temb[NODES_MAX * D];   // emb@W2^T

// ---------------------------------------------------------------------------
// K1: Y[v] = X[v] @ W^T (+ b1 + b2 when biased). One thread per node,
// acc[64] in registers, W transposed in shared (row stride 68 floats = 272B,
// 16B-aligned so float4 LDS works; all lanes read same address -> broadcast).
// ---------------------------------------------------------------------------
__global__ void __launch_bounds__(128) k_gemm(
    const float* __restrict__ X, const float* __restrict__ W,
    const float* __restrict__ b1, const float* __restrict__ b2,
    int out_sel, int n)
{
    __shared__ float sWt[D * 68];
    __shared__ float sB[D];

    for (int idx = threadIdx.x; idx < D * D; idx += blockDim.x) {
        int j = idx >> 6;       // row of W
        int k = idx & 63;       // col of W
        sWt[k * 68 + j] = W[idx];
    }
    if (threadIdx.x < D) {
        sB[threadIdx.x] = (b1 != nullptr)
                        ? (b1[threadIdx.x] + b2[threadIdx.x]) : 0.0f;
    }
    __syncthreads();

    int v = blockIdx.x * blockDim.x + threadIdx.x;
    if (v >= n) return;

    float acc[D];
    #pragma unroll
    for (int j = 0; j < D; j++) acc[j] = sB[j];

    const float4* xr = reinterpret_cast<const float4*>(X + (size_t)v * D);
    #pragma unroll
    for (int kk = 0; kk < D / 4; kk++) {
        float4 f = xr[kk];
        float fs[4] = {f.x, f.y, f.z, f.w};
        #pragma unroll
        for (int q = 0; q < 4; q++) {
            float fk = fs[q];
            const float4* wr =
                reinterpret_cast<const float4*>(&sWt[(kk * 4 + q) * 68]);
            #pragma unroll
            for (int j4 = 0; j4 < D / 4; j4++) {
                float4 w = wr[j4];
                acc[j4 * 4 + 0] = fmaf(fk, w.x, acc[j4 * 4 + 0]);
                acc[j4 * 4 + 1] = fmaf(fk, w.y, acc[j4 * 4 + 1]);
                acc[j4 * 4 + 2] = fmaf(fk, w.z, acc[j4 * 4 + 2]);
                acc[j4 * 4 + 3] = fmaf(fk, w.w, acc[j4 * 4 + 3]);
            }
        }
    }

    float* Y = out_sel ? g_temb : g_base;
    float4* yr = reinterpret_cast<float4*>(Y + (size_t)v * D);
    #pragma unroll
    for (int j4 = 0; j4 < D / 4; j4++) {
        yr[j4] = make_float4(acc[j4 * 4 + 0], acc[j4 * 4 + 1],
                             acc[j4 * 4 + 2], acc[j4 * 4 + 3]);
    }
}

// ---------------------------------------------------------------------------
// K2: edge scatter. 16 lanes per edge, each lane moves one float4:
//   g_base[dst] += g_temb[src]   via red.global.add.v4.f32
// g_temb (25.6MB) is L2-resident, so gathers hit L2.
// ---------------------------------------------------------------------------
__global__ void __launch_bounds__(256) k_edges(
    const int* __restrict__ esrc, const int* __restrict__ edst, int ne)
{
    unsigned tid = blockIdx.x * 256u + threadIdx.x;
    unsigned e = tid >> 4;
    if (e >= (unsigned)ne) return;
    unsigned l = tid & 15u;

    int s = __ldg(esrc + e);
    int d = __ldg(edst + e);

    const float4 v = *reinterpret_cast<const float4*>(
        g_temb + (size_t)s * D + l * 4);
    float* p = g_base + (size_t)d * D + l * 4;

    asm volatile("red.global.add.v4.f32 [%0], {%1, %2, %3, %4};"
                 :: "l"(p), "f"(v.x), "f"(v.y), "f"(v.z), "f"(v.w)
                 : "memory");
}

// ---------------------------------------------------------------------------
// K3: out[c] = sum_v relu(g_base[v][c]).  d_out must be pre-zeroed (k_zero).
// ---------------------------------------------------------------------------
__global__ void __launch_bounds__(64) k_zero(float* __restrict__ out)
{
    out[threadIdx.x] = 0.0f;
}

__global__ void __launch_bounds__(256) k_reduce(
    float* __restrict__ out, int n)
{
    int c = threadIdx.x & 63;        // output column
    int g = threadIdx.x >> 6;        // 0..3 row-group within block
    float s = 0.0f;
    for (int v = blockIdx.x * 4 + g; v < n; v += gridDim.x * 4)
        s += fmaxf(g_base[(size_t)v * D + c], 0.0f);

    __shared__ float red[256];
    red[threadIdx.x] = s;
    __syncthreads();
    if (threadIdx.x < 128) red[threadIdx.x] += red[threadIdx.x + 128];
    __syncthreads();
    if (threadIdx.x < 64) {
        float t = red[threadIdx.x] + red[threadIdx.x + 64];
        atomicAdd(&out[threadIdx.x], t);
    }
}

// ---------------------------------------------------------------------------
// Launch
// ---------------------------------------------------------------------------
extern "C" void kernel_launch(void* const* d_in, const int* in_sizes, int n_in,
                              void* d_out, int out_size)
{
    const float* feat = (const float*)d_in[0];
    const float* emb  = (const float*)d_in[1];
    const float* W1   = (const float*)d_in[2];
    const float* b1   = (const float*)d_in[3];
    const float* W2   = (const float*)d_in[4];
    const float* b2   = (const float*)d_in[5];
    const int* esrc   = (const int*)d_in[6];
    const int* edst   = (const int*)d_in[7];
    float* out = (float*)d_out;

    int n  = in_sizes[0] / D;     // 100000
    int ne = in_sizes[6];         // 1600000

    int gb = (n + 127) / 128;
    // g_base = feat @ W1^T + b1 + b2
    k_gemm<<<gb, 128>>>(feat, W1, b1, b2, /*out_sel=*/0, n);
    // g_temb = emb @ W2^T
    k_gemm<<<gb, 128>>>(emb, W2, nullptr, nullptr, /*out_sel=*/1, n);

    // edge scatter: g_base[dst] += g_temb[src]
    unsigned et = (unsigned)ne * 16u;
    k_edges<<<(et + 255u) / 256u, 256>>>(esrc, edst, ne);

    // final relu + column reduce
    k_zero<<<1, 64>>>(out);
    k_reduce<<<256, 256>>>(out, n);
}

// round 12
// speedup vs baseline: 1.1914x; 1.1914x over previous
#include <cuda_runtime.h>

#define NODES_MAX 100000
#define D 64
#define SCAN_CHUNK 1024
#define NB_MAX 128   // ceil(100000/1024)=98 <= 128

// Scratch (device globals; no runtime allocation)
__device__ float g_base[NODES_MAX * D];   // feat@W1^T + b1 + b2
__device__ float g_temb[NODES_MAX * D];   // emb@W2^T
__device__ int   g_count[NODES_MAX];      // in-degree histogram
__device__ int   g_start[NODES_MAX];      // CSR exclusive offsets
__device__ int   g_cursor[NODES_MAX];     // fill cursors
__device__ int   g_bsum[NB_MAX];          // scan block sums
__device__ int   g_eidx[1600000];         // CSR edge source ids

// Packed f32x2 helpers (sm_103a; .rn rounding == scalar fmaf bitwise)
__device__ __forceinline__ unsigned long long f2_pack(float lo, float hi)
{
    unsigned long long d;
    asm("mov.b64 %0, {%1, %2};" : "=l"(d) : "f"(lo), "f"(hi));
    return d;
}
__device__ __forceinline__ unsigned long long f2_fma(
    unsigned long long a, unsigned long long b, unsigned long long c)
{
    unsigned long long d;
    asm("fma.rn.f32x2 %0, %1, %2, %3;" : "=l"(d) : "l"(a), "l"(b), "l"(c));
    return d;
}

// ---------------------------------------------------------------------------
// Zero counters + output accumulator
// ---------------------------------------------------------------------------
__global__ void __launch_bounds__(256) k_zero_all(float* __restrict__ out, int n)
{
    int i = blockIdx.x * 256 + threadIdx.x;
    if (i < n) g_count[i] = 0;
    if (i < 64) out[i] = 0.0f;
}

// ---------------------------------------------------------------------------
// Histogram of destination nodes (int REDG, spread addresses)
// ---------------------------------------------------------------------------
__global__ void __launch_bounds__(256) k_hist(const int* __restrict__ edst, int ne)
{
    int e = blockIdx.x * 256 + threadIdx.x;
    if (e < ne) atomicAdd(&g_count[edst[e]], 1);
}

// ---------------------------------------------------------------------------
// Scan step 1: per-chunk (1024 items) exclusive scan + chunk totals
// ---------------------------------------------------------------------------
__global__ void __launch_bounds__(256) k_scan1(int n)
{
    __shared__ int ssum[256];
    int t = threadIdx.x;
    int base = blockIdx.x * SCAN_CHUNK + t * 4;

    int v[4];
    int tsum = 0;
    #pragma unroll
    for (int j = 0; j < 4; j++) {
        v[j] = (base + j < n) ? g_count[base + j] : 0;
        tsum += v[j];
    }
    ssum[t] = tsum;
    __syncthreads();
    #pragma unroll
    for (int off = 1; off < 256; off <<= 1) {
        int add = (t >= off) ? ssum[t - off] : 0;
        __syncthreads();
        ssum[t] += add;
        __syncthreads();
    }
    int excl = ssum[t] - tsum;   // exclusive prefix of this thread's group
    int run = excl;
    #pragma unroll
    for (int j = 0; j < 4; j++) {
        if (base + j < n) g_start[base + j] = run;
        run += v[j];
    }
    if (t == 255) g_bsum[blockIdx.x] = ssum[255];
}

// ---------------------------------------------------------------------------
// Scan step 2: single-block exclusive scan of chunk totals
// ---------------------------------------------------------------------------
__global__ void __launch_bounds__(128) k_scan2(int nb)
{
    __shared__ int s[128];
    int t = threadIdx.x;
    int val = (t < nb) ? g_bsum[t] : 0;
    s[t] = val;
    __syncthreads();
    #pragma unroll
    for (int off = 1; off < 128; off <<= 1) {
        int add = (t >= off) ? s[t - off] : 0;
        __syncthreads();
        s[t] += add;
        __syncthreads();
    }
    if (t < nb) g_bsum[t] = s[t] - val;   // exclusive
}

// ---------------------------------------------------------------------------
// Scan step 3: add chunk offsets; init cursors
// ---------------------------------------------------------------------------
__global__ void __launch_bounds__(256) k_scan3(int n)
{
    int i = blockIdx.x * 256 + threadIdx.x;
    if (i >= n) return;
    int val = g_start[i] + g_bsum[i >> 10];
    g_start[i] = val;
    g_cursor[i] = val;
}

// ---------------------------------------------------------------------------
// CSR fill: scatter source ids by destination
// ---------------------------------------------------------------------------
__global__ void __launch_bounds__(256) k_fill(
    const int* __restrict__ esrc, const int* __restrict__ edst, int ne)
{
    int e = blockIdx.x * 256 + threadIdx.x;
    if (e >= ne) return;
    int d = edst[e];
    int pos = atomicAdd(&g_cursor[d], 1);
    g_eidx[pos] = esrc[e];
}

// ---------------------------------------------------------------------------
// GEMM: Y[v] = X[v] @ W^T (+ b1 + b2 when biased). One thread per node.
// Accumulators are 32 packed f32x2 pairs (pair i = output cols 2i, 2i+1);
// FFMA2 halves fma-pipe issue. W transposed in shared (stride 68 floats =
// 272B, 16B-aligned; all lanes read same address -> broadcast, LDS.128).
// ---------------------------------------------------------------------------
__global__ void __launch_bounds__(128) k_gemm(
    const float* __restrict__ X, const float* __restrict__ W,
    const float* __restrict__ b1, const float* __restrict__ b2,
    int out_sel, int n)
{
    __shared__ __align__(16) float sWt[D * 68];
    __shared__ float sB[D];

    for (int idx = threadIdx.x; idx < D * D; idx += blockDim.x) {
        int j = idx >> 6;       // row of W (output col)
        int k = idx & 63;       // col of W (input dim)
        sWt[k * 68 + j] = W[idx];
    }
    if (threadIdx.x < D) {
        sB[threadIdx.x] = (b1 != nullptr)
                        ? (b1[threadIdx.x] + b2[threadIdx.x]) : 0.0f;
    }
    __syncthreads();

    int v = blockIdx.x * blockDim.x + threadIdx.x;
    if (v >= n) return;

    unsigned long long acc2[D / 2];
    #pragma unroll
    for (int j2 = 0; j2 < D / 2; j2++)
        acc2[j2] = f2_pack(sB[2 * j2], sB[2 * j2 + 1]);

    const float4* xr = reinterpret_cast<const float4*>(X + (size_t)v * D);
    #pragma unroll
    for (int kk = 0; kk < D / 4; kk++) {
        float4 f = xr[kk];
        float fs[4] = {f.x, f.y, f.z, f.w};
        #pragma unroll
        for (int q = 0; q < 4; q++) {
            unsigned long long fk2 = f2_pack(fs[q], fs[q]);
            const ulonglong2* wr = reinterpret_cast<const ulonglong2*>(
                &sWt[(kk * 4 + q) * 68]);
            #pragma unroll
            for (int p = 0; p < 16; p++) {
                ulonglong2 w = wr[p];       // floats 4p..4p+3 = pairs 2p, 2p+1
                acc2[2 * p + 0] = f2_fma(fk2, w.x, acc2[2 * p + 0]);
                acc2[2 * p + 1] = f2_fma(fk2, w.y, acc2[2 * p + 1]);
            }
        }
    }

    float* Y = out_sel ? g_temb : g_base;
    ulonglong2* yr = reinterpret_cast<ulonglong2*>(Y + (size_t)v * D);
    #pragma unroll
    for (int p = 0; p < 16; p++)
        yr[p] = make_ulonglong2(acc2[2 * p + 0], acc2[2 * p + 1]);
}

// ---------------------------------------------------------------------------
// Fused gather + relu + column reduce.
// 16 lanes per node (each lane one float4 of the row), 16 nodes per block.
//   row(v) = g_base[v] + sum_{e in CSR(v)} g_temb[src(e)]
//   out[c] += relu(row(v)[c])
// No float atomics to global except 64 per block.
// ---------------------------------------------------------------------------
__global__ void __launch_bounds__(256) k_gather(float* __restrict__ out, int n)
{
    __shared__ float sout[D];

    int tid = threadIdx.x;
    if (tid < D) sout[tid] = 0.0f;
    __syncthreads();

    int node = blockIdx.x * 16 + (tid >> 4);
    int lane = tid & 15;

    if (node < n) {
        const float4* base4 = reinterpret_cast<const float4*>(g_base);
        const float4* temb4 = reinterpret_cast<const float4*>(g_temb);

        float4 acc = base4[(size_t)node * 16 + lane];
        int st  = g_start[node];
        int cnt = g_count[node];
        for (int i = 0; i < cnt; i++) {
            int s = g_eidx[st + i];
            float4 t = temb4[(size_t)s * 16 + lane];
            acc.x += t.x; acc.y += t.y; acc.z += t.z; acc.w += t.w;
        }
        acc.x = fmaxf(acc.x, 0.0f);
        acc.y = fmaxf(acc.y, 0.0f);
        acc.z = fmaxf(acc.z, 0.0f);
        acc.w = fmaxf(acc.w, 0.0f);

        int c = lane * 4;
        atomicAdd(&sout[c + 0], acc.x);
        atomicAdd(&sout[c + 1], acc.y);
        atomicAdd(&sout[c + 2], acc.z);
        atomicAdd(&sout[c + 3], acc.w);
    }
    __syncthreads();
    if (tid < D) atomicAdd(&out[tid], sout[tid]);
}

// ---------------------------------------------------------------------------
// Launch
// ---------------------------------------------------------------------------
extern "C" void kernel_launch(void* const* d_in, const int* in_sizes, int n_in,
                              void* d_out, int out_size)
{
    const float* feat = (const float*)d_in[0];
    const float* emb  = (const float*)d_in[1];
    const float* W1   = (const float*)d_in[2];
    const float* b1   = (const float*)d_in[3];
    const float* W2   = (const float*)d_in[4];
    const float* b2   = (const float*)d_in[5];
    const int* esrc   = (const int*)d_in[6];
    const int* edst   = (const int*)d_in[7];
    float* out = (float*)d_out;

    int n  = in_sizes[0] / D;     // 100000
    int ne = in_sizes[6];         // 1600000
    int nb = (n + SCAN_CHUNK - 1) / SCAN_CHUNK;   // 98

    int gn256 = (n + 255) / 256;
    int ge256 = (ne + 255) / 256;

    // CSR build (int ops only)
    k_zero_all<<<gn256, 256>>>(out, n);
    k_hist<<<ge256, 256>>>(edst, ne);
    k_scan1<<<nb, 256>>>(n);
    k_scan2<<<1, 128>>>(nb);
    k_scan3<<<gn256, 256>>>(n);
    k_fill<<<ge256, 256>>>(esrc, edst, ne);

    // Dense transforms
    int gb = (n + 127) / 128;
    k_gemm<<<gb, 128>>>(feat, W1, b1, b2, /*out_sel=*/0, n);
    k_gemm<<<gb, 128>>>(emb, W2, nullptr, nullptr, /*out_sel=*/1, n);

    // Fused gather + relu + graph reduce
    k_gather<<<(n + 15) / 16, 256>>>(out, n);
}

// round 13
// speedup vs baseline: 1.3125x; 1.1017x over previous
#include <cuda_runtime.h>

#define NODES_MAX 100000
#define D 64
#define SCAN_CHUNK 1024
#define NB_MAX 128   // ceil(100000/1024)=98 <= 128

// Scratch (device globals; no runtime allocation)
__device__ float g_base[NODES_MAX * D];   // feat@W1^T + b1 + b2
__device__ float g_temb[NODES_MAX * D];   // emb@W2^T
__device__ int   g_count[NODES_MAX];      // in-degree histogram
__device__ int   g_start[NODES_MAX];      // CSR offsets (becomes END after fill)
__device__ int   g_bsum[NB_MAX];          // scan chunk sums
__device__ int   g_eidx[1600000];         // CSR edge source ids

// Packed f32x2 helpers (sm_103a; .rn rounding == scalar fmaf bitwise)
__device__ __forceinline__ unsigned long long f2_pack(float lo, float hi)
{
    unsigned long long d;
    asm("mov.b64 %0, {%1, %2};" : "=l"(d) : "f"(lo), "f"(hi));
    return d;
}
__device__ __forceinline__ unsigned long long f2_fma(
    unsigned long long a, unsigned long long b, unsigned long long c)
{
    unsigned long long d;
    asm("fma.rn.f32x2 %0, %1, %2, %3;" : "=l"(d) : "l"(a), "l"(b), "l"(c));
    return d;
}

// ---------------------------------------------------------------------------
// Launch 1 — GEMM (both transforms in one launch, grid.y selects):
//   y=0: g_base = feat@W1^T + b1 + b2   (also zeroes g_count and out)
//   y=1: g_temb = emb @W2^T
// One thread per node; 32 packed f32x2 accumulators (FFMA2 halves fma issue).
// W transposed in shared (stride 68 floats = 272B, 16B-aligned -> LDS.128,
// same-address across lanes -> broadcast).
// ---------------------------------------------------------------------------
__global__ void __launch_bounds__(128) k_gemm(
    const float* __restrict__ feat, const float* __restrict__ emb,
    const float* __restrict__ W1, const float* __restrict__ W2,
    const float* __restrict__ b1, const float* __restrict__ b2,
    float* __restrict__ out, int n)
{
    const int sel = blockIdx.y;
    const float* X = sel ? emb : feat;
    const float* W = sel ? W2 : W1;

    __shared__ __align__(16) float sWt[D * 68];
    __shared__ float sB[D];

    // Fold the zeroing of g_count / out into the y=0 GEMM blocks.
    int gidx = blockIdx.x * 128 + threadIdx.x;
    if (sel == 0) {
        if (gidx < n) g_count[gidx] = 0;
        if (gidx < 64) out[gidx] = 0.0f;
    }

    for (int idx = threadIdx.x; idx < D * D; idx += blockDim.x) {
        int j = idx >> 6;       // row of W (output col)
        int k = idx & 63;       // col of W (input dim)
        sWt[k * 68 + j] = W[idx];
    }
    if (threadIdx.x < D) {
        sB[threadIdx.x] = sel ? 0.0f
                              : (b1[threadIdx.x] + b2[threadIdx.x]);
    }
    __syncthreads();

    int v = gidx;
    if (v >= n) return;

    unsigned long long acc2[D / 2];
    #pragma unroll
    for (int j2 = 0; j2 < D / 2; j2++)
        acc2[j2] = f2_pack(sB[2 * j2], sB[2 * j2 + 1]);

    const float4* xr = reinterpret_cast<const float4*>(X + (size_t)v * D);
    #pragma unroll
    for (int kk = 0; kk < D / 4; kk++) {
        float4 f = xr[kk];
        float fs[4] = {f.x, f.y, f.z, f.w};
        #pragma unroll
        for (int q = 0; q < 4; q++) {
            unsigned long long fk2 = f2_pack(fs[q], fs[q]);
            const ulonglong2* wr = reinterpret_cast<const ulonglong2*>(
                &sWt[(kk * 4 + q) * 68]);
            #pragma unroll
            for (int p = 0; p < 16; p++) {
                ulonglong2 w = wr[p];       // floats 4p..4p+3 = pairs 2p, 2p+1
                acc2[2 * p + 0] = f2_fma(fk2, w.x, acc2[2 * p + 0]);
                acc2[2 * p + 1] = f2_fma(fk2, w.y, acc2[2 * p + 1]);
            }
        }
    }

    float* Y = sel ? g_temb : g_base;
    ulonglong2* yr = reinterpret_cast<ulonglong2*>(Y + (size_t)v * D);
    #pragma unroll
    for (int p = 0; p < 16; p++)
        yr[p] = make_ulonglong2(acc2[2 * p + 0], acc2[2 * p + 1]);
}

// ---------------------------------------------------------------------------
// Launch 2 — histogram of destination nodes (int REDG, spread addresses)
// ---------------------------------------------------------------------------
__global__ void __launch_bounds__(256) k_hist(const int* __restrict__ edst, int ne)
{
    int e = blockIdx.x * 256 + threadIdx.x;
    if (e < ne) atomicAdd(&g_count[edst[e]], 1);
}

// ---------------------------------------------------------------------------
// Launch 3 — per-chunk (1024 items) exclusive scan + chunk totals
// ---------------------------------------------------------------------------
__global__ void __launch_bounds__(256) k_scan1(int n)
{
    __shared__ int ssum[256];
    int t = threadIdx.x;
    int base = blockIdx.x * SCAN_CHUNK + t * 4;

    int v[4];
    int tsum = 0;
    #pragma unroll
    for (int j = 0; j < 4; j++) {
        v[j] = (base + j < n) ? g_count[base + j] : 0;
        tsum += v[j];
    }
    ssum[t] = tsum;
    __syncthreads();
    #pragma unroll
    for (int off = 1; off < 256; off <<= 1) {
        int add = (t >= off) ? ssum[t - off] : 0;
        __syncthreads();
        ssum[t] += add;
        __syncthreads();
    }
    int excl = ssum[t] - tsum;   // exclusive prefix of this thread's group
    int run = excl;
    #pragma unroll
    for (int j = 0; j < 4; j++) {
        if (base + j < n) g_start[base + j] = run;
        run += v[j];
    }
    if (t == 255) g_bsum[blockIdx.x] = ssum[255];
}

// ---------------------------------------------------------------------------
// Launch 4 — add chunk offsets (inline lookback: each block reduces the <=98
// preceding chunk totals itself; kills the separate 1-block scan2 launch).
// Block b covers nodes [256b, 256b+256) -> all in chunk b>>2.
// ---------------------------------------------------------------------------
__global__ void __launch_bounds__(256) k_scan3(int n)
{
    __shared__ int soff[8];
    int t = threadIdx.x;
    int chunk = blockIdx.x >> 2;

    int v = (t < chunk) ? g_bsum[t] : 0;   // chunk <= 97 < 256
    #pragma unroll
    for (int o = 16; o; o >>= 1) v += __shfl_down_sync(0xFFFFFFFFu, v, o);
    if ((t & 31) == 0) soff[t >> 5] = v;
    __syncthreads();
    if (t == 0) {
        int s = 0;
        #pragma unroll
        for (int w = 0; w < 8; w++) s += soff[w];
        soff[0] = s;
    }
    __syncthreads();
    int off = soff[0];

    int i = blockIdx.x * 256 + t;
    if (i < n) g_start[i] += off;
}

// ---------------------------------------------------------------------------
// Launch 5 — CSR fill. Cursor-free: bump g_start itself; after this kernel
// g_start[v] = end of v's range, and start = end - g_count[v].
// ---------------------------------------------------------------------------
__global__ void __launch_bounds__(256) k_fill(
    const int* __restrict__ esrc, const int* __restrict__ edst, int ne)
{
    int e = blockIdx.x * 256 + threadIdx.x;
    if (e >= ne) return;
    int d = edst[e];
    int pos = atomicAdd(&g_start[d], 1);
    g_eidx[pos] = esrc[e];
}

// ---------------------------------------------------------------------------
// Launch 6 — fused gather + relu + column reduce.
// 16 lanes per node (each lane one float4 of the row), 16 nodes per block.
//   row(v) = g_base[v] + sum_{e in CSR(v)} g_temb[src(e)]
//   out[c] += relu(row(v)[c])
// Edge loop unrolled x2 for two independent load chains per lane.
// ---------------------------------------------------------------------------
__global__ void __launch_bounds__(256) k_gather(float* __restrict__ out, int n)
{
    __shared__ float sout[D];

    int tid = threadIdx.x;
    if (tid < D) sout[tid] = 0.0f;
    __syncthreads();

    int node = blockIdx.x * 16 + (tid >> 4);
    int lane = tid & 15;

    if (node < n) {
        const float4* base4 = reinterpret_cast<const float4*>(g_base);
        const float4* temb4 = reinterpret_cast<const float4*>(g_temb);

        float4 acc = base4[(size_t)node * 16 + lane];
        int cnt = g_count[node];
        int st  = g_start[node] - cnt;    // g_start is END after k_fill

        int i = 0;
        for (; i + 2 <= cnt; i += 2) {
            int s0 = g_eidx[st + i];
            int s1 = g_eidx[st + i + 1];
            float4 t0 = temb4[(size_t)s0 * 16 + lane];
            float4 t1 = temb4[(size_t)s1 * 16 + lane];
            acc.x += t0.x; acc.y += t0.y; acc.z += t0.z; acc.w += t0.w;
            acc.x += t1.x; acc.y += t1.y; acc.z += t1.z; acc.w += t1.w;
        }
        if (i < cnt) {
            int s = g_eidx[st + i];
            float4 t = temb4[(size_t)s * 16 + lane];
            acc.x += t.x; acc.y += t.y; acc.z += t.z; acc.w += t.w;
        }

        acc.x = fmaxf(acc.x, 0.0f);
        acc.y = fmaxf(acc.y, 0.0f);
        acc.z = fmaxf(acc.z, 0.0f);
        acc.w = fmaxf(acc.w, 0.0f);

        int c = lane * 4;
        atomicAdd(&sout[c + 0], acc.x);
        atomicAdd(&sout[c + 1], acc.y);
        atomicAdd(&sout[c + 2], acc.z);
        atomicAdd(&sout[c + 3], acc.w);
    }
    __syncthreads();
    if (tid < D) atomicAdd(&out[tid], sout[tid]);
}

// ---------------------------------------------------------------------------
// Launch
// ---------------------------------------------------------------------------
extern "C" void kernel_launch(void* const* d_in, const int* in_sizes, int n_in,
                              void* d_out, int out_size)
{
    const float* feat = (const float*)d_in[0];
    const float* emb  = (const float*)d_in[1];
    const float* W1   = (const float*)d_in[2];
    const float* b1   = (const float*)d_in[3];
    const float* W2   = (const float*)d_in[4];
    const float* b2   = (const float*)d_in[5];
    const int* esrc   = (const int*)d_in[6];
    const int* edst   = (const int*)d_in[7];
    float* out = (float*)d_out;

    int n  = in_sizes[0] / D;     // 100000
    int ne = in_sizes[6];         // 1600000
    int nb = (n + SCAN_CHUNK - 1) / SCAN_CHUNK;   // 98

    int gb    = (n + 127) / 128;
    int gn256 = (n + 255) / 256;
    int ge256 = (ne + 255) / 256;

    // 1) both GEMMs + zero(count, out) in one launch
    k_gemm<<<dim3(gb, 2), 128>>>(feat, emb, W1, W2, b1, b2, out, n);
    // 2) in-degree histogram
    k_hist<<<ge256, 256>>>(edst, ne);
    // 3) per-chunk scan
    k_scan1<<<nb, 256>>>(n);
    // 4) chunk-offset add with inline lookback (no separate scan2)
    k_scan3<<<gn256, 256>>>(n);
    // 5) CSR fill (cursor-free)
    k_fill<<<ge256, 256>>>(esrc, edst, ne);
    // 6) fused gather + relu + graph reduce
    k_gather<<<(n + 15) / 16, 256>>>(out, n);
}